// round 3
// baseline (speedup 1.0000x reference)
#include <cuda_runtime.h>
#include <cuda_bf16.h>
#include <math.h>

// ---------------- constants ----------------
#define TT   2048
#define DD   1024
#define HH   16
#define HS   64
#define EE   8
#define KK   2
#define LL   2
#define CAP  512
#define FF   4096   // 4*D

// ---------------- scratch (device globals; no allocation allowed) ----------
__device__ float g_x  [TT * DD];
__device__ float g_xn [TT * DD];
__device__ float g_qkv[TT * 3 * DD];
__device__ float g_av [TT * DD];
__device__ float g_de [EE * CAP * DD];
__device__ float g_h  [EE * CAP * FF];
__device__ float g_eo [EE * CAP * DD];
__device__ int   g_topi[TT * KK];
__device__ int   g_pos [TT * KK];
__device__ float g_gate[TT * KK];

// ---------------- embedding ----------------
__global__ void embed_kernel(const int* __restrict__ ids,
                             const float* __restrict__ tok,
                             const float* __restrict__ pe,
                             float* __restrict__ x) {
    int t = blockIdx.x, j = threadIdx.x;           // 256 threads, one float4 each
    int id = ids[t];
    float4 a = ((const float4*)(tok + (size_t)id * DD))[j];
    float4 b = ((const float4*)(pe  + (size_t)t  * DD))[j];
    a.x += b.x; a.y += b.y; a.z += b.z; a.w += b.w;
    ((float4*)(x + (size_t)t * DD))[j] = a;
}

// ---------------- elementwise residual add: x += s ----------------
__global__ void add_kernel(float* __restrict__ x, const float* __restrict__ s) {
    int t = blockIdx.x, j = threadIdx.x;
    float4 v = ((const float4*)(x + (size_t)t * DD))[j];
    float4 a = ((const float4*)(s + (size_t)t * DD))[j];
    v.x += a.x; v.y += a.y; v.z += a.z; v.w += a.w;
    ((float4*)(x + (size_t)t * DD))[j] = v;
}

// ---------------- layernorm (row per block, 256 threads) ----------------
__global__ void ln_kernel(const float* __restrict__ x,
                          const float* __restrict__ w,
                          const float* __restrict__ b,
                          float* __restrict__ out) {
    int t = blockIdx.x, j = threadIdx.x;
    float4 v = ((const float4*)(x + (size_t)t * DD))[j];
    float s = v.x + v.y + v.z + v.w;
    float q = v.x * v.x + v.y * v.y + v.z * v.z + v.w * v.w;
#pragma unroll
    for (int o = 16; o > 0; o >>= 1) {
        s += __shfl_xor_sync(0xffffffffu, s, o);
        q += __shfl_xor_sync(0xffffffffu, q, o);
    }
    __shared__ float ss[8], sq[8];
    if ((j & 31) == 0) { ss[j >> 5] = s; sq[j >> 5] = q; }
    __syncthreads();
    float S = 0.f, Q = 0.f;
#pragma unroll
    for (int k = 0; k < 8; k++) { S += ss[k]; Q += sq[k]; }
    float mean = S * (1.f / DD);
    float var  = Q * (1.f / DD) - mean * mean;
    float rstd = rsqrtf(var + 1e-5f);
    float4 wv = ((const float4*)w)[j];
    float4 bv = ((const float4*)b)[j];
    float4 o4;
    o4.x = (v.x - mean) * rstd * wv.x + bv.x;
    o4.y = (v.y - mean) * rstd * wv.y + bv.y;
    o4.z = (v.z - mean) * rstd * wv.z + bv.z;
    o4.w = (v.w - mean) * rstd * wv.w + bv.w;
    ((float4*)(out + (size_t)t * DD))[j] = o4;
}

// ---------------- generic tiled GEMM: C = A(MxK) * B(NxK)^T (+bias)(relu) ----
// NOTE: C must never alias A or B.
template <bool RELU>
__global__ __launch_bounds__(256)
void gemm_kernel(const float* __restrict__ A, const float* __restrict__ Bm,
                 const float* __restrict__ bias,
                 float* C,
                 int M, int N, int Kd,
                 long long aB, long long bB, long long biasB, long long cB) {
    int bz = blockIdx.z;
    A  += (long long)bz * aB;
    Bm += (long long)bz * bB;
    C  += (long long)bz * cB;
    if (bias) bias += (long long)bz * biasB;

    int rowBase = blockIdx.y * 128;
    int colBase = blockIdx.x * 128;

    __shared__ float As[16][128];
    __shared__ float Bs[16][128];

    int tid = threadIdx.x;
    int tx = tid & 15, ty = tid >> 4;
    int lrow = tid >> 2;          // 0..63
    int lcol = (tid & 3) * 4;     // 0,4,8,12

    float acc[8][8];
#pragma unroll
    for (int i = 0; i < 8; i++)
#pragma unroll
        for (int j = 0; j < 8; j++) acc[i][j] = 0.f;

    for (int k0 = 0; k0 < Kd; k0 += 16) {
#pragma unroll
        for (int j = 0; j < 2; j++) {
            int r = lrow + j * 64;
            float4 a = *(const float4*)(A  + (size_t)(rowBase + r) * Kd + k0 + lcol);
            As[lcol + 0][r] = a.x; As[lcol + 1][r] = a.y;
            As[lcol + 2][r] = a.z; As[lcol + 3][r] = a.w;
            float4 bb = *(const float4*)(Bm + (size_t)(colBase + r) * Kd + k0 + lcol);
            Bs[lcol + 0][r] = bb.x; Bs[lcol + 1][r] = bb.y;
            Bs[lcol + 2][r] = bb.z; Bs[lcol + 3][r] = bb.w;
        }
        __syncthreads();
#pragma unroll
        for (int kk = 0; kk < 16; kk++) {
            float4 a0 = *(const float4*)&As[kk][ty * 4];
            float4 a1 = *(const float4*)&As[kk][64 + ty * 4];
            float4 b0 = *(const float4*)&Bs[kk][tx * 4];
            float4 b1 = *(const float4*)&Bs[kk][64 + tx * 4];
            float ar[8] = {a0.x, a0.y, a0.z, a0.w, a1.x, a1.y, a1.z, a1.w};
            float br[8] = {b0.x, b0.y, b0.z, b0.w, b1.x, b1.y, b1.z, b1.w};
#pragma unroll
            for (int i = 0; i < 8; i++)
#pragma unroll
                for (int j = 0; j < 8; j++) acc[i][j] += ar[i] * br[j];
        }
        __syncthreads();
    }

#pragma unroll
    for (int i = 0; i < 8; i++) {
        int r = rowBase + ((i < 4) ? (ty * 4 + i) : (64 + ty * 4 + (i - 4)));
#pragma unroll
        for (int jj = 0; jj < 2; jj++) {
            int c = colBase + jj * 64 + tx * 4;
            float4 v;
            v.x = acc[i][jj * 4 + 0]; v.y = acc[i][jj * 4 + 1];
            v.z = acc[i][jj * 4 + 2]; v.w = acc[i][jj * 4 + 3];
            if (bias) {
                v.x += bias[c]; v.y += bias[c + 1];
                v.z += bias[c + 2]; v.w += bias[c + 3];
            }
            if (RELU) {
                v.x = fmaxf(v.x, 0.f); v.y = fmaxf(v.y, 0.f);
                v.z = fmaxf(v.z, 0.f); v.w = fmaxf(v.w, 0.f);
            }
            *(float4*)(C + (size_t)r * N + c) = v;
        }
    }
}

// ---------------- RoPE in-place on q,k inside qkv ----------------
__global__ void rope_kernel(float* __restrict__ qkv) {
    int t = blockIdx.x, h = blockIdx.y, i = threadIdx.x;   // 32 threads
    float div = expf((float)(-2 * i) * (logf(10000.f) / 64.f));
    float ang = (float)t * div;
    float s, c;
    sincosf(ang, &s, &c);
#pragma unroll
    for (int which = 0; which < 2; which++) {
        float* b = qkv + (size_t)t * (3 * DD) + which * DD + h * HS;
        float t1 = b[i], t2 = b[i + 32];
        b[i]      = t1 * c - t2 * s;
        b[i + 32] = t2 * c + t1 * s;
    }
}

// ---------------- flash attention: block = (qtile of 128, head), thread = 1 query
// OUTPUT LAYOUT: av is written in (H, T, HS) contiguous order ("bhtd"), matching
// the reference's av.transpose(0,2,1,3).reshape(B,T,D) before the out-projection.
__global__ __launch_bounds__(128)
void attn_kernel(const float* __restrict__ qkv, float* __restrict__ av) {
    int h = blockIdx.y;
    int qtile = blockIdx.x;
    int qt = qtile * 128 + threadIdx.x;

    __shared__ float4 Ks[64][16];
    __shared__ float4 Vs[64][16];

    float4 qv[16];
    const float4* qrow = (const float4*)(qkv + (size_t)qt * (3 * DD) + h * HS);
#pragma unroll
    for (int i = 0; i < 16; i++) qv[i] = qrow[i];

    float o[64];
#pragma unroll
    for (int d = 0; d < 64; d++) o[d] = 0.f;
    float m = -1e30f, l = 0.f;

    int nkt = 2 * qtile + 2;
    for (int kt = 0; kt < nkt; kt++) {
        __syncthreads();
#pragma unroll
        for (int j = 0; j < 8; j++) {
            int idx = threadIdx.x + j * 128;   // 0..1023
            int s = idx >> 4, c = idx & 15;
            int gs = kt * 64 + s;
            const float4* kr = (const float4*)(qkv + (size_t)gs * (3 * DD) + DD + h * HS);
            const float4* vr = (const float4*)(qkv + (size_t)gs * (3 * DD) + 2 * DD + h * HS);
            Ks[s][c] = kr[c];
            Vs[s][c] = vr[c];
        }
        __syncthreads();

#pragma unroll
        for (int sub = 0; sub < 4; sub++) {
            float sc[16];
            float tmax = -1e30f;
#pragma unroll
            for (int s = 0; s < 16; s++) {
                int ls = sub * 16 + s;
                float acc = 0.f;
#pragma unroll
                for (int i = 0; i < 16; i++) {
                    float4 k4 = Ks[ls][i];
                    acc += qv[i].x * k4.x + qv[i].y * k4.y + qv[i].z * k4.z + qv[i].w * k4.w;
                }
                int gs = kt * 64 + ls;
                acc = (gs <= qt) ? acc * 0.125f : -1e30f;
                sc[s] = acc;
                tmax = fmaxf(tmax, acc);
            }
            float nm = fmaxf(m, tmax);
            float scale = __expf(m - nm);
            l *= scale;
#pragma unroll
            for (int d = 0; d < 64; d++) o[d] *= scale;
#pragma unroll
            for (int s = 0; s < 16; s++) {
                int ls = sub * 16 + s;
                float p = __expf(sc[s] - nm);
                l += p;
#pragma unroll
                for (int i = 0; i < 16; i++) {
                    float4 v4 = Vs[ls][i];
                    o[i * 4 + 0] += p * v4.x;
                    o[i * 4 + 1] += p * v4.y;
                    o[i * 4 + 2] += p * v4.z;
                    o[i * 4 + 3] += p * v4.w;
                }
            }
            m = nm;
        }
    }
    float inv = 1.f / l;
    // bhtd layout: row index = h*T + t, contiguous HS
    float* orow = av + ((size_t)h * TT + qt) * HS;
#pragma unroll
    for (int i = 0; i < 16; i++) {
        float4 v;
        v.x = o[i * 4 + 0] * inv; v.y = o[i * 4 + 1] * inv;
        v.z = o[i * 4 + 2] * inv; v.w = o[i * 4 + 3] * inv;
        ((float4*)orow)[i] = v;
    }
}

// ---------------- router: logits, noisy top-2, gates ----------------
__global__ void router_kernel(const float* __restrict__ xn,
                              const float* __restrict__ rw, const float* __restrict__ rb,
                              const float* __restrict__ nw, const float* __restrict__ nb,
                              const float* __restrict__ noise,
                              int* __restrict__ topi, float* __restrict__ gate) {
    int t = blockIdx.x;
    int wid = threadIdx.x >> 5, lane = threadIdx.x & 31;   // 8 warps = 8 experts
    __shared__ float noisy[EE];
    const float4* x4 = (const float4*)(xn + (size_t)t * DD);
    const float4* r4 = (const float4*)(rw + (size_t)wid * DD);
    const float4* n4 = (const float4*)(nw + (size_t)wid * DD);
    float a = 0.f, c = 0.f;
    for (int j = lane; j < DD / 4; j += 32) {
        float4 xv = x4[j], rv = r4[j], nv = n4[j];
        a += xv.x * rv.x + xv.y * rv.y + xv.z * rv.z + xv.w * rv.w;
        c += xv.x * nv.x + xv.y * nv.y + xv.z * nv.z + xv.w * nv.w;
    }
#pragma unroll
    for (int o = 16; o > 0; o >>= 1) {
        a += __shfl_xor_sync(0xffffffffu, a, o);
        c += __shfl_xor_sync(0xffffffffu, c, o);
    }
    if (lane == 0) {
        float logit = a + rb[wid];
        float nl = c + nb[wid];
        float sp = (nl > 20.f) ? nl : log1pf(expf(nl));
        noisy[wid] = logit + noise[(size_t)t * EE + wid] * sp;
    }
    __syncthreads();
    if (threadIdx.x == 0) {
        int i0 = 0; float v0 = noisy[0];
#pragma unroll
        for (int e = 1; e < EE; e++) if (noisy[e] > v0) { v0 = noisy[e]; i0 = e; }
        int i1 = -1; float v1 = -1e30f;
#pragma unroll
        for (int e = 0; e < EE; e++) if (e != i0 && noisy[e] > v1) { v1 = noisy[e]; i1 = e; }
        float g0 = 1.f / (1.f + expf(v1 - v0));
        topi[t * 2] = i0; topi[t * 2 + 1] = i1;
        gate[t * 2] = g0; gate[t * 2 + 1] = 1.f - g0;
    }
}

// ---------------- capacity rank / position (warp e handles expert e) --------
__global__ void rank_kernel(const int* __restrict__ topi, int* __restrict__ pos) {
    int e = threadIdx.x >> 5, lane = threadIdx.x & 31;     // 256 threads = 8 warps
    int base = 0;
    for (int c = 0; c < (TT * KK) / 32; c++) {
        int i = c * 32 + lane;
        int ef = topi[i];
        bool mt = (ef == e);
        unsigned msk = __ballot_sync(0xffffffffu, mt);
        if (mt) {
            int r = base + __popc(msk & ((1u << lane) - 1u));
            pos[i] = (r < CAP) ? (e * CAP + r) : -1;
        }
        base += __popc(msk);
    }
}

// ---------------- dispatch gather ----------------
__global__ void dispatch_kernel(const float* __restrict__ xn,
                                const int* __restrict__ pos,
                                float* __restrict__ de) {
    int i = blockIdx.x;
    int p = pos[i];
    if (p < 0) return;
    int t = i >> 1;
    ((float4*)(de + (size_t)p * DD))[threadIdx.x] =
        ((const float4*)(xn + (size_t)t * DD))[threadIdx.x];
}

// ---------------- combine scatter + residual ----------------
__global__ void combine_kernel(float* __restrict__ x,
                               const float* __restrict__ eo,
                               const int* __restrict__ pos,
                               const float* __restrict__ gate) {
    int t = blockIdx.x, j = threadIdx.x;
    int p0 = pos[2 * t], p1 = pos[2 * t + 1];
    float g0 = gate[2 * t], g1 = gate[2 * t + 1];
    float4 v = ((const float4*)(x + (size_t)t * DD))[j];
    if (p0 >= 0) {
        float4 a = ((const float4*)(eo + (size_t)p0 * DD))[j];
        v.x += g0 * a.x; v.y += g0 * a.y; v.z += g0 * a.z; v.w += g0 * a.w;
    }
    if (p1 >= 0) {
        float4 a = ((const float4*)(eo + (size_t)p1 * DD))[j];
        v.x += g1 * a.x; v.y += g1 * a.y; v.z += g1 * a.z; v.w += g1 * a.w;
    }
    ((float4*)(x + (size_t)t * DD))[j] = v;
}

// ---------------- host side ----------------
static void run_gemm(const float* A, const float* B, const float* bias,
                     float* C, int M, int N, int Kd, int batch,
                     long long aB, long long bB, long long biasB, long long cB,
                     bool relu) {
    dim3 grid(N / 128, M / 128, batch), blk(256);
    if (relu)
        gemm_kernel<true><<<grid, blk>>>(A, B, bias, C, M, N, Kd, aB, bB, biasB, cB);
    else
        gemm_kernel<false><<<grid, blk>>>(A, B, bias, C, M, N, Kd, aB, bB, biasB, cB);
}

extern "C" void kernel_launch(void* const* d_in, const int* in_sizes, int n_in,
                              void* d_out, int out_size) {
    const int*   ids      = (const int*)  d_in[0];
    const float* noise    = (const float*)d_in[1];
    const float* tok_emb  = (const float*)d_in[2];
    const float* pos_emb  = (const float*)d_in[3];
    const float* ln1_w    = (const float*)d_in[4];
    const float* ln1_b    = (const float*)d_in[5];
    const float* ln2_w    = (const float*)d_in[6];
    const float* ln2_b    = (const float*)d_in[7];
    const float* qkv_w    = (const float*)d_in[8];
    const float* out_w    = (const float*)d_in[9];
    const float* router_w = (const float*)d_in[10];
    const float* router_b = (const float*)d_in[11];
    const float* noise_w  = (const float*)d_in[12];
    const float* noise_b  = (const float*)d_in[13];
    const float* e_w1     = (const float*)d_in[14];
    const float* e_b1     = (const float*)d_in[15];
    const float* e_w2     = (const float*)d_in[16];
    const float* e_b2     = (const float*)d_in[17];
    const float* lnf_w    = (const float*)d_in[18];
    const float* lnf_b    = (const float*)d_in[19];

    float *x, *xn, *qkv, *av, *de, *h, *eo, *gate;
    int *topi, *pos;
    cudaGetSymbolAddress((void**)&x,    g_x);
    cudaGetSymbolAddress((void**)&xn,   g_xn);
    cudaGetSymbolAddress((void**)&qkv,  g_qkv);
    cudaGetSymbolAddress((void**)&av,   g_av);
    cudaGetSymbolAddress((void**)&de,   g_de);
    cudaGetSymbolAddress((void**)&h,    g_h);
    cudaGetSymbolAddress((void**)&eo,   g_eo);
    cudaGetSymbolAddress((void**)&topi, g_topi);
    cudaGetSymbolAddress((void**)&pos,  g_pos);
    cudaGetSymbolAddress((void**)&gate, g_gate);

    embed_kernel<<<TT, 256>>>(ids, tok_emb, pos_emb, x);

    for (int l = 0; l < LL; l++) {
        // attention block
        ln_kernel<<<TT, 256>>>(x, ln1_w + (size_t)l * DD, ln1_b + (size_t)l * DD, xn);
        run_gemm(xn, qkv_w + (size_t)l * 3 * DD * DD, nullptr, qkv,
                 TT, 3 * DD, DD, 1, 0, 0, 0, 0, false);
        rope_kernel<<<dim3(TT, HH), 32>>>(qkv);
        attn_kernel<<<dim3(TT / 128, HH), 128>>>(qkv, av);
        // out-projection into xn (xn is dead here), then residual add (no aliasing)
        run_gemm(av, out_w + (size_t)l * DD * DD, nullptr, xn,
                 TT, DD, DD, 1, 0, 0, 0, 0, false);
        add_kernel<<<TT, 256>>>(x, xn);

        // MoE block
        ln_kernel<<<TT, 256>>>(x, ln2_w + (size_t)l * DD, ln2_b + (size_t)l * DD, xn);
        router_kernel<<<TT, 256>>>(xn,
                                   router_w + (size_t)l * EE * DD, router_b + (size_t)l * EE,
                                   noise_w  + (size_t)l * EE * DD, noise_b  + (size_t)l * EE,
                                   noise + (size_t)l * TT * EE, topi, gate);
        rank_kernel<<<1, 256>>>(topi, pos);
        dispatch_kernel<<<TT * KK, 256>>>(xn, pos, de);
        run_gemm(de, e_w1 + (size_t)l * EE * FF * DD, e_b1 + (size_t)l * EE * FF,
                 h, CAP, FF, DD, EE,
                 (long long)CAP * DD, (long long)FF * DD, FF, (long long)CAP * FF, true);
        run_gemm(h, e_w2 + (size_t)l * EE * DD * FF, e_b2 + (size_t)l * EE * DD,
                 eo, CAP, DD, FF, EE,
                 (long long)CAP * FF, (long long)DD * FF, DD, (long long)CAP * DD, false);
        combine_kernel<<<TT, 256>>>(x, eo, pos, gate);
    }

    ln_kernel<<<TT, 256>>>(x, lnf_w, lnf_b, (float*)d_out);
}